// round 9
// baseline (speedup 1.0000x reference)
#include <cuda_runtime.h>

// 2-qubit dense gate on 24-qubit state, batch=4 (innermost, contiguous).
// Flat float index = qindex * 4 + b.  qubit k -> bit (23-k) of qindex.
// support (5,12) -> qindex bits 18 and 11.
//
// R7: persistent grid (148 SMs x 8 blocks, grid-stride) removes the 0.84
// partial-wave tail, + 2-stage software pipeline (prefetch next iter's 4
// loads before storing current) keeps per-warp load queues continuously
// occupied. Gate in smem; streaming stores. regs ~48 is fine: occ was
// proven flat across 62-84%.

static constexpr unsigned REST_BITS = 22;          // 24 - 2 support qubits
static constexpr unsigned N_REST    = 1u << REST_BITS;
static constexpr unsigned BIT_C     = 1u << 18;    // qubit 5
static constexpr unsigned BIT_D     = 1u << 11;    // qubit 12

static constexpr unsigned THREADS   = 256;
static constexpr unsigned BLOCKS    = 148 * 8;     // one full resident wave

__device__ __forceinline__ unsigned expand_rest(unsigned r)
{
    return (r & 0x7FFu) | ((r & 0x1F800u) << 1) | ((r >> 17) << 19);
}

__global__ void __launch_bounds__(THREADS)
quantum_gate2_kernel(const float4* __restrict__ in,
                     const float*  __restrict__ gate,
                     float4*       __restrict__ out)
{
    __shared__ float gs[16];
    if (threadIdx.x < 16) gs[threadIdx.x] = gate[threadIdx.x];
    __syncthreads();

    const unsigned stride = BLOCKS * THREADS;
    unsigned r  = blockIdx.x * THREADS + threadIdx.x;
    unsigned qb = expand_rest(r);

    // Stage-0 loads.
    float4 v0 = __ldcs(in + qb);
    float4 v1 = __ldcs(in + (qb | BIT_D));
    float4 v2 = __ldcs(in + (qb | BIT_C));
    float4 v3 = __ldcs(in + (qb | BIT_C | BIT_D));

    while (true) {
        const unsigned rn = r + stride;
        const bool more = rn < N_REST;
        unsigned qbn = 0;
        float4 n0, n1, n2, n3;
        if (more) {
            qbn = expand_rest(rn);
            n0 = __ldcs(in + qbn);                    // prefetch next iter
            n1 = __ldcs(in + (qbn | BIT_D));
            n2 = __ldcs(in + (qbn | BIT_C));
            n3 = __ldcs(in + (qbn | BIT_C | BIT_D));
        }

        float4* pout = out + qb;
        float4 o;
        o.x = gs[0]*v0.x + gs[1]*v1.x + gs[2]*v2.x + gs[3]*v3.x;
        o.y = gs[0]*v0.y + gs[1]*v1.y + gs[2]*v2.y + gs[3]*v3.y;
        o.z = gs[0]*v0.z + gs[1]*v1.z + gs[2]*v2.z + gs[3]*v3.z;
        o.w = gs[0]*v0.w + gs[1]*v1.w + gs[2]*v2.w + gs[3]*v3.w;
        __stcs(pout, o);

        o.x = gs[4]*v0.x + gs[5]*v1.x + gs[6]*v2.x + gs[7]*v3.x;
        o.y = gs[4]*v0.y + gs[5]*v1.y + gs[6]*v2.y + gs[7]*v3.y;
        o.z = gs[4]*v0.z + gs[5]*v1.z + gs[6]*v2.z + gs[7]*v3.z;
        o.w = gs[4]*v0.w + gs[5]*v1.w + gs[6]*v2.w + gs[7]*v3.w;
        __stcs(pout + BIT_D, o);

        o.x = gs[8]*v0.x + gs[9]*v1.x + gs[10]*v2.x + gs[11]*v3.x;
        o.y = gs[8]*v0.y + gs[9]*v1.y + gs[10]*v2.y + gs[11]*v3.y;
        o.z = gs[8]*v0.z + gs[9]*v1.z + gs[10]*v2.z + gs[11]*v3.z;
        o.w = gs[8]*v0.w + gs[9]*v1.w + gs[10]*v2.w + gs[11]*v3.w;
        __stcs(pout + BIT_C, o);

        o.x = gs[12]*v0.x + gs[13]*v1.x + gs[14]*v2.x + gs[15]*v3.x;
        o.y = gs[12]*v0.y + gs[13]*v1.y + gs[14]*v2.y + gs[15]*v3.y;
        o.z = gs[12]*v0.z + gs[13]*v1.z + gs[14]*v2.z + gs[15]*v3.z;
        o.w = gs[12]*v0.w + gs[13]*v1.w + gs[14]*v2.w + gs[15]*v3.w;
        __stcs(pout + (BIT_C + BIT_D), o);

        if (!more) break;
        r = rn; qb = qbn;
        v0 = n0; v1 = n1; v2 = n2; v3 = n3;
    }
}

extern "C" void kernel_launch(void* const* d_in, const int* in_sizes, int n_in,
                              void* d_out, int out_size)
{
    const float4* state = (const float4*)d_in[0];
    const float*  gate  = (const float*)d_in[1];
    float4*       out   = (float4*)d_out;

    quantum_gate2_kernel<<<BLOCKS, THREADS>>>(state, gate, out);
}

// round 12
// speedup vs baseline: 1.0220x; 1.0220x over previous
#include <cuda_runtime.h>

// 2-qubit dense gate on 24-qubit state, batch=4 (innermost, contiguous).
// Flat float index = qindex * 4 + b.  qubit k -> bit (23-k) of qindex.
// support (5,12) -> qindex bits 18 and 11.
//
// R11 (= R8 retry after container-level infra failure): best-known config
// (smem gate, 32 regs, store-as-computed, streaming stores, plain loads)
// with 512-thread blocks. Each block's four access streams become 8KiB
// contiguous -> better DRAM row locality; half the block count. All other
// levers proven pinned at the ~6.4TB/s mixed-stream DRAM ceiling.

static constexpr unsigned REST_BITS = 22;          // 24 - 2 support qubits
static constexpr unsigned N_REST    = 1u << REST_BITS;
static constexpr unsigned BIT_C     = 1u << 18;    // qubit 5
static constexpr unsigned BIT_D     = 1u << 11;    // qubit 12

static constexpr unsigned THREADS   = 512;

__global__ void __launch_bounds__(THREADS, 4)
quantum_gate2_kernel(const float4* __restrict__ in,
                     const float*  __restrict__ gate,
                     float4*       __restrict__ out)
{
    __shared__ float gs[16];
    if (threadIdx.x < 16) gs[threadIdx.x] = gate[threadIdx.x];
    __syncthreads();

    const unsigned r = blockIdx.x * THREADS + threadIdx.x;
    // Expand rest index: insert zero bits at qindex positions 11 and 18.
    const unsigned low = r & 0x7FFu;           // bits 0..10
    const unsigned mid = (r >> 11) & 0x3Fu;    // -> qindex bits 12..17
    const unsigned hi  = r >> 17;              // -> qindex bits 19..23
    const unsigned qb  = low | (mid << 12) | (hi << 19);

    const float4* pin  = in  + qb;
    float4*       pout = out + qb;

    // Front-batch the 4 independent 16B loads (per-thread MLP=4).
    const float4 v0 = pin[0u];                // c=0,d=0
    const float4 v1 = pin[BIT_D];             // c=0,d=1
    const float4 v2 = pin[BIT_C];             // c=1,d=0
    const float4 v3 = pin[BIT_C + BIT_D];     // c=1,d=1

    float4 o;

    o.x = gs[0]*v0.x + gs[1]*v1.x + gs[2]*v2.x + gs[3]*v3.x;
    o.y = gs[0]*v0.y + gs[1]*v1.y + gs[2]*v2.y + gs[3]*v3.y;
    o.z = gs[0]*v0.z + gs[1]*v1.z + gs[2]*v2.z + gs[3]*v3.z;
    o.w = gs[0]*v0.w + gs[1]*v1.w + gs[2]*v2.w + gs[3]*v3.w;
    __stcs(pout, o);

    o.x = gs[4]*v0.x + gs[5]*v1.x + gs[6]*v2.x + gs[7]*v3.x;
    o.y = gs[4]*v0.y + gs[5]*v1.y + gs[6]*v2.y + gs[7]*v3.y;
    o.z = gs[4]*v0.z + gs[5]*v1.z + gs[6]*v2.z + gs[7]*v3.z;
    o.w = gs[4]*v0.w + gs[5]*v1.w + gs[6]*v2.w + gs[7]*v3.w;
    __stcs(pout + BIT_D, o);

    o.x = gs[8]*v0.x + gs[9]*v1.x + gs[10]*v2.x + gs[11]*v3.x;
    o.y = gs[8]*v0.y + gs[9]*v1.y + gs[10]*v2.y + gs[11]*v3.y;
    o.z = gs[8]*v0.z + gs[9]*v1.z + gs[10]*v2.z + gs[11]*v3.z;
    o.w = gs[8]*v0.w + gs[9]*v1.w + gs[10]*v2.w + gs[11]*v3.w;
    __stcs(pout + BIT_C, o);

    o.x = gs[12]*v0.x + gs[13]*v1.x + gs[14]*v2.x + gs[15]*v3.x;
    o.y = gs[12]*v0.y + gs[13]*v1.y + gs[14]*v2.y + gs[15]*v3.y;
    o.z = gs[12]*v0.z + gs[13]*v1.z + gs[14]*v2.z + gs[15]*v3.z;
    o.w = gs[12]*v0.w + gs[13]*v1.w + gs[14]*v2.w + gs[15]*v3.w;
    __stcs(pout + (BIT_C + BIT_D), o);
}

extern "C" void kernel_launch(void* const* d_in, const int* in_sizes, int n_in,
                              void* d_out, int out_size)
{
    const float4* state = (const float4*)d_in[0];
    const float*  gate  = (const float*)d_in[1];
    float4*       out   = (float4*)d_out;

    const unsigned blocks = N_REST / THREADS;   // 2^22 / 512 = 8192
    quantum_gate2_kernel<<<blocks, THREADS>>>(state, gate, out);
}

// round 13
// speedup vs baseline: 1.0304x; 1.0082x over previous
#include <cuda_runtime.h>

// 2-qubit dense gate on 24-qubit state, batch=4 (innermost, contiguous).
// Flat float index = qindex * 4 + b.  qubit k -> bit (23-k) of qindex.
// support (5,12) -> qindex bits 18 and 11.
//
// R13: block-size sweep, last sensitive knob. Measured: 256thr -> 80.9%
// DRAM, 512thr -> 76.8% (L1tex queue contention). Test 128thr/block
// (16 blocks/SM, same 2048 thr/SM): shorter per-CTA LDG bursts into the
// L1tex queue, smoother DRAM arrival. Otherwise the proven R5 config:
// smem gate, 32 regs, store-as-computed, plain loads, streaming stores.

static constexpr unsigned REST_BITS = 22;          // 24 - 2 support qubits
static constexpr unsigned N_REST    = 1u << REST_BITS;
static constexpr unsigned BIT_C     = 1u << 18;    // qubit 5
static constexpr unsigned BIT_D     = 1u << 11;    // qubit 12

static constexpr unsigned THREADS   = 128;

__global__ void __launch_bounds__(THREADS, 16)
quantum_gate2_kernel(const float4* __restrict__ in,
                     const float*  __restrict__ gate,
                     float4*       __restrict__ out)
{
    __shared__ float gs[16];
    if (threadIdx.x < 16) gs[threadIdx.x] = gate[threadIdx.x];
    __syncthreads();

    const unsigned r = blockIdx.x * THREADS + threadIdx.x;
    // Expand rest index: insert zero bits at qindex positions 11 and 18.
    const unsigned low = r & 0x7FFu;           // bits 0..10
    const unsigned mid = (r >> 11) & 0x3Fu;    // -> qindex bits 12..17
    const unsigned hi  = r >> 17;              // -> qindex bits 19..23
    const unsigned qb  = low | (mid << 12) | (hi << 19);

    const float4* pin  = in  + qb;
    float4*       pout = out + qb;

    // Front-batch the 4 independent 16B loads (per-thread MLP=4).
    const float4 v0 = pin[0u];                // c=0,d=0
    const float4 v1 = pin[BIT_D];             // c=0,d=1
    const float4 v2 = pin[BIT_C];             // c=1,d=0
    const float4 v3 = pin[BIT_C + BIT_D];     // c=1,d=1

    float4 o;

    o.x = gs[0]*v0.x + gs[1]*v1.x + gs[2]*v2.x + gs[3]*v3.x;
    o.y = gs[0]*v0.y + gs[1]*v1.y + gs[2]*v2.y + gs[3]*v3.y;
    o.z = gs[0]*v0.z + gs[1]*v1.z + gs[2]*v2.z + gs[3]*v3.z;
    o.w = gs[0]*v0.w + gs[1]*v1.w + gs[2]*v2.w + gs[3]*v3.w;
    __stcs(pout, o);

    o.x = gs[4]*v0.x + gs[5]*v1.x + gs[6]*v2.x + gs[7]*v3.x;
    o.y = gs[4]*v0.y + gs[5]*v1.y + gs[6]*v2.y + gs[7]*v3.y;
    o.z = gs[4]*v0.z + gs[5]*v1.z + gs[6]*v2.z + gs[7]*v3.z;
    o.w = gs[4]*v0.w + gs[5]*v1.w + gs[6]*v2.w + gs[7]*v3.w;
    __stcs(pout + BIT_D, o);

    o.x = gs[8]*v0.x + gs[9]*v1.x + gs[10]*v2.x + gs[11]*v3.x;
    o.y = gs[8]*v0.y + gs[9]*v1.y + gs[10]*v2.y + gs[11]*v3.y;
    o.z = gs[8]*v0.z + gs[9]*v1.z + gs[10]*v2.z + gs[11]*v3.z;
    o.w = gs[8]*v0.w + gs[9]*v1.w + gs[10]*v2.w + gs[11]*v3.w;
    __stcs(pout + BIT_C, o);

    o.x = gs[12]*v0.x + gs[13]*v1.x + gs[14]*v2.x + gs[15]*v3.x;
    o.y = gs[12]*v0.y + gs[13]*v1.y + gs[14]*v2.y + gs[15]*v3.y;
    o.z = gs[12]*v0.z + gs[13]*v1.z + gs[14]*v2.z + gs[15]*v3.z;
    o.w = gs[12]*v0.w + gs[13]*v1.w + gs[14]*v2.w + gs[15]*v3.w;
    __stcs(pout + (BIT_C + BIT_D), o);
}

extern "C" void kernel_launch(void* const* d_in, const int* in_sizes, int n_in,
                              void* d_out, int out_size)
{
    const float4* state = (const float4*)d_in[0];
    const float*  gate  = (const float*)d_in[1];
    float4*       out   = (float4*)d_out;

    const unsigned blocks = N_REST / THREADS;   // 2^22 / 128 = 32768
    quantum_gate2_kernel<<<blocks, THREADS>>>(state, gate, out);
}

// round 15
// speedup vs baseline: 1.0336x; 1.0031x over previous
#include <cuda_runtime.h>

// 2-qubit dense gate on 24-qubit state, batch=4 (innermost, contiguous).
// Flat float index = qindex * 4 + b.  qubit k -> bit (23-k) of qindex.
// support (5,12) -> qindex bits 18 and 11.
//
// FINAL (R5 config, ncu-best of 9 measurements at 75.0us device time):
// 1 rest-index/thread, gate in shared memory (LDS broadcast), store-as-
// computed (4 live accumulators), __launch_bounds__(256,8) -> 32 regs,
// occ ~81%, streaming stores. Pinned at the DRAM mixed read/write
// turnaround ceiling: 6.4 TB/s (~80% of spec). Verified limits: L2 39%,
// issue 16%, block sizes 128/256/512 bracketed, per-thread ILP and
// cache-hint variants all neutral or worse. Traffic is irreducible
// (512 MiB total, one touch per byte each way).

static constexpr unsigned REST_BITS = 22;          // 24 - 2 support qubits
static constexpr unsigned N_REST    = 1u << REST_BITS;
static constexpr unsigned BIT_C     = 1u << 18;    // qubit 5
static constexpr unsigned BIT_D     = 1u << 11;    // qubit 12

__global__ void __launch_bounds__(256, 8)
quantum_gate2_kernel(const float4* __restrict__ in,
                     const float*  __restrict__ gate,
                     float4*       __restrict__ out)
{
    __shared__ float gs[16];
    if (threadIdx.x < 16) gs[threadIdx.x] = gate[threadIdx.x];
    __syncthreads();

    const unsigned r = blockIdx.x * blockDim.x + threadIdx.x;
    // Expand rest index: insert zero bits at qindex positions 11 and 18.
    const unsigned low = r & 0x7FFu;           // bits 0..10
    const unsigned mid = (r >> 11) & 0x3Fu;    // -> qindex bits 12..17
    const unsigned hi  = r >> 17;              // -> qindex bits 19..23
    const unsigned qb  = low | (mid << 12) | (hi << 19);

    const float4* pin  = in  + qb;
    float4*       pout = out + qb;

    // Front-batch the 4 independent 16B loads (per-thread MLP=4).
    const float4 v0 = pin[0u];                // c=0,d=0
    const float4 v1 = pin[BIT_D];             // c=0,d=1
    const float4 v2 = pin[BIT_C];             // c=1,d=0
    const float4 v3 = pin[BIT_C + BIT_D];     // c=1,d=1

    float4 o;

    o.x = gs[0]*v0.x + gs[1]*v1.x + gs[2]*v2.x + gs[3]*v3.x;
    o.y = gs[0]*v0.y + gs[1]*v1.y + gs[2]*v2.y + gs[3]*v3.y;
    o.z = gs[0]*v0.z + gs[1]*v1.z + gs[2]*v2.z + gs[3]*v3.z;
    o.w = gs[0]*v0.w + gs[1]*v1.w + gs[2]*v2.w + gs[3]*v3.w;
    __stcs(pout, o);

    o.x = gs[4]*v0.x + gs[5]*v1.x + gs[6]*v2.x + gs[7]*v3.x;
    o.y = gs[4]*v0.y + gs[5]*v1.y + gs[6]*v2.y + gs[7]*v3.y;
    o.z = gs[4]*v0.z + gs[5]*v1.z + gs[6]*v2.z + gs[7]*v3.z;
    o.w = gs[4]*v0.w + gs[5]*v1.w + gs[6]*v2.w + gs[7]*v3.w;
    __stcs(pout + BIT_D, o);

    o.x = gs[8]*v0.x + gs[9]*v1.x + gs[10]*v2.x + gs[11]*v3.x;
    o.y = gs[8]*v0.y + gs[9]*v1.y + gs[10]*v2.y + gs[11]*v3.y;
    o.z = gs[8]*v0.z + gs[9]*v1.z + gs[10]*v2.z + gs[11]*v3.z;
    o.w = gs[8]*v0.w + gs[9]*v1.w + gs[10]*v2.w + gs[11]*v3.w;
    __stcs(pout + BIT_C, o);

    o.x = gs[12]*v0.x + gs[13]*v1.x + gs[14]*v2.x + gs[15]*v3.x;
    o.y = gs[12]*v0.y + gs[13]*v1.y + gs[14]*v2.y + gs[15]*v3.y;
    o.z = gs[12]*v0.z + gs[13]*v1.z + gs[14]*v2.z + gs[15]*v3.z;
    o.w = gs[12]*v0.w + gs[13]*v1.w + gs[14]*v2.w + gs[15]*v3.w;
    __stcs(pout + (BIT_C + BIT_D), o);
}

extern "C" void kernel_launch(void* const* d_in, const int* in_sizes, int n_in,
                              void* d_out, int out_size)
{
    const float4* state = (const float4*)d_in[0];
    const float*  gate  = (const float*)d_in[1];
    float4*       out   = (float4*)d_out;

    const unsigned threads = 256;
    const unsigned blocks  = N_REST / threads;   // 2^22 / 256 = 16384
    quantum_gate2_kernel<<<blocks, threads>>>(state, gate, out);
}